// round 9
// baseline (speedup 1.0000x reference)
#include <cuda_runtime.h>
#include <math.h>

// ============================================================================
// Sparse e3nn tensor product, uvu mode — f32x2-packed row-pair version.
// irreps1 = 128x0e+128x1o+128x2e (x1: [Z,1152]), irreps2 = 1x0e+1x1o+1x2e.
// 83-entry hardcoded sparsity; coefficients computed on HOST (fp64) and
// passed by value. Each warp: 32 channels x 2 rows per iteration, 4 pairs,
// double-buffered cp.async, packed f32x2 math, no block barriers.
// ============================================================================

#define NE 83
#define NT 11

struct Coefs { float c[NE]; };

// ---------------- host-side tables (sparsity pattern) ----------------------
static const int hTL1[NT] = {0,0,0,1,1,1,1,2,2,2,2};
static const int hTL2[NT] = {0,1,2,0,1,1,2,0,1,2,2};
static const int hTL3[NT] = {0,1,2,1,0,2,1,2,1,0,2};
static const double hTALPHA[NT] = {
  0.5773502691896258, 0.8660254037844386, 1.1180339887498949,
  0.8660254037844386, 0.5773502691896258, 1.1180339887498949,
  0.8660254037844386, 1.1180339887498949, 0.8660254037844386,
  0.5773502691896258, 1.1180339887498949};

static const unsigned char hENT_T[NE] = {
  0, 1,1,1, 2,2,2,2,2, 3,3,3, 4,4,4,
  5,5,5,5,5,5,5,5,5,5,5,
  6,6,6,6,6,6,6,6,6,6,6,
  7,7,7,7,7,
  8,8,8,8,8,8,8,8,8,8,8,
  9,9,9,9,9,
  10,10,10,10,10,10,10,10,10,10,10,10,10,10,10,10,10,10,10,10,10,10,10,10,10};
static const unsigned char hENT_I[NE] = {
  0, 0,0,0, 0,0,0,0,0, 0,1,2, 0,1,2,
  1,1,1,2,0,2,0,2,0,2,0,
  1,1,1,2,0,2,0,2,0,2,0,
  0,1,2,3,4,
  2,2,2,3,1,3,1,4,4,0,0,
  0,1,2,3,4,
  2,2,2,3,1,2,2,4,0,3,1,3,1,3,1,3,1,3,1,4,0,4,0,4,0};
static const unsigned char hENT_J[NE] = {
  0, 0,1,2, 0,1,2,3,4, 0,0,0, 0,1,2,
  1,2,0,1,1,2,0,2,0,0,2,
  2,3,1,2,2,3,1,4,4,0,0,
  0,0,0,0,0,
  1,2,0,1,1,2,0,2,0,2,0,
  0,1,2,3,4,
  2,3,1,2,2,4,0,2,2,3,1,3,1,1,3,4,4,0,0,3,3,1,1,4,0};
static const unsigned char hENT_K[NE] = {
  0, 0,1,2, 0,1,2,3,4, 0,1,2, 0,0,0,
  2,3,1,3,1,2,2,4,4,0,0,
  1,2,0,2,0,1,1,2,0,0,2,
  0,1,2,3,4,
  1,2,0,2,0,1,1,2,0,0,2,
  0,0,0,0,0,
  2,3,1,3,1,4,0,4,0,2,2,4,4,0,0,3,1,1,3,3,1,1,3,2,2};

// ---------------- host coefficient computation (fp64) ----------------------
static double hfact(int n) {
  double r = 1.0;
  for (int i = 2; i <= n; ++i) r *= (double)i;
  return r;
}

static double hsu2cg(int j1,int m1,int j2,int m2,int j3,int m3) {
  if (m1 + m2 != m3) return 0.0;
  int vmin = -j1+j2+m3; if (-j1+m1 > vmin) vmin = -j1+m1; if (vmin < 0) vmin = 0;
  int vmax = j2+j3+m1; if (j3-j1+j2 < vmax) vmax = j3-j1+j2; if (j3+m3 < vmax) vmax = j3+m3;
  double C = sqrt((2.0*j3+1.0)*hfact(j3+j1-j2)*hfact(j3-j1+j2)*hfact(j1+j2-j3)
                  *hfact(j3+m3)*hfact(j3-m3)
                  /(hfact(j1+j2+j3+1)*hfact(j1-m1)*hfact(j1+m1)*hfact(j2-m2)*hfact(j2+m2)));
  double S = 0.0;
  for (int v = vmin; v <= vmax; ++v) {
    double s = ((v + j2 + m2) & 1) ? -1.0 : 1.0;
    S += s * hfact(j2+j3+m1-v)*hfact(j1-m1+v)
         /(hfact(v)*hfact(j3-j1+j2-v)*hfact(j3+m3-v)*hfact(v+j1-j2-m3));
  }
  return C * S;
}

static void hqent(int l, int r, int c, double* qr, double* qi) {
  const double inv2 = 0.7071067811865476;
  double re = 0.0, im = 0.0;
  int m = r - l;
  if (m < 0) {
    if (c == l - m) re = inv2;
    if (c == l + m) im = -inv2;
  } else if (m == 0) {
    if (c == l) re = 1.0;
  } else {
    double s = (m & 1) ? -1.0 : 1.0;
    if (c == l + m) re = s * inv2;
    if (c == l - m) im = s * inv2;
  }
  if (l == 1) { double t0 = re; re = im; im = -t0; }
  else if (l == 2) { re = -re; im = -im; }
  *qr = re; *qi = im;
}

static void compute_coefs(Coefs* out) {
  for (int t = 0; t < NT; ++t) {
    int l1 = hTL1[t], l2 = hTL2[t], l3 = hTL3[t];
    int d1 = 2*l1+1, d2 = 2*l2+1, d3 = 2*l3+1;
    double cgc[125], cre[125];
    for (int i = 0; i < d1; ++i)
      for (int k = 0; k < d2; ++k)
        for (int nn = 0; nn < d3; ++nn)
          cgc[(i*d2+k)*d3+nn] = hsu2cg(l1, i-l1, l2, k-l2, l3, nn-l3);
    double nrm = 0.0;
    for (int j = 0; j < d1; ++j)
      for (int l = 0; l < d2; ++l)
        for (int m = 0; m < d3; ++m) {
          double acc = 0.0;
          for (int i = 0; i < d1; ++i)
            for (int k = 0; k < d2; ++k) {
              int nn = (i-l1) + (k-l2) + l3;
              if (nn < 0 || nn >= d3) continue;
              double cv = cgc[(i*d2+k)*d3+nn];
              if (cv == 0.0) continue;
              double q1r,q1i,q2r,q2i,q3r,q3i;
              hqent(l1, i,  j, &q1r, &q1i);
              if (q1r == 0.0 && q1i == 0.0) continue;
              hqent(l2, k,  l, &q2r, &q2i);
              if (q2r == 0.0 && q2i == 0.0) continue;
              hqent(l3, nn, m, &q3r, &q3i);
              double tr = q1r*q2r - q1i*q2i;
              double ti = q1r*q2i + q1i*q2r;
              acc += cv * (tr*q3r + ti*q3i);
            }
          cre[(j*d2+l)*d3+m] = acc;
          nrm += acc*acc;
        }
    double scale = hTALPHA[t] / sqrt(nrm);
    for (int e = 0; e < NE; ++e) {
      if (hENT_T[e] != t) continue;
      int idx = ((int)hENT_I[e]*d2 + (int)hENT_J[e])*d3 + (int)hENT_K[e];
      out->c[e] = (float)(cre[idx] * scale);
    }
  }
}

// ---------------------------------------------------------------------------
// Device helpers
// ---------------------------------------------------------------------------
typedef unsigned long long u64;

__device__ __forceinline__ u64 pack2(float lo, float hi) {
  u64 r; asm("mov.b64 %0, {%1, %2};" : "=l"(r) : "f"(lo), "f"(hi)); return r;
}
__device__ __forceinline__ u64 bcast2(float v) {
  u64 r; asm("mov.b64 %0, {%1, %1};" : "=l"(r) : "f"(v)); return r;
}
__device__ __forceinline__ void unpack2(u64 v, float& lo, float& hi) {
  asm("mov.b64 {%0, %1}, %2;" : "=f"(lo), "=f"(hi) : "l"(v));
}
__device__ __forceinline__ u64 mul2(u64 a, u64 b) {
  u64 r; asm("mul.rn.f32x2 %0, %1, %2;" : "=l"(r) : "l"(a), "l"(b)); return r;
}
__device__ __forceinline__ u64 fma2(u64 a, u64 b, u64 c) {
  u64 r; asm("fma.rn.f32x2 %0, %1, %2, %3;" : "=l"(r) : "l"(a), "l"(b), "l"(c)); return r;
}

#define CPA16(dst, src) \
  asm volatile("cp.async.cg.shared.global [%0], [%1], 16;" :: \
               "r"((unsigned)__cvta_generic_to_shared(dst)), "l"(src))

__device__ __forceinline__ void issue_slice(float4* sb4, const float4* src,
                                            int q, int lane) {
  if (lane < 8)  CPA16(sb4 + lane,      src + 8*q + lane);
  if (lane < 24) CPA16(sb4 + 8 + lane,  src + 32 + 24*q + lane);
  CPA16(sb4 + 32 + lane, src + 128 + 40*q + lane);
  if (lane < 8)  CPA16(sb4 + 64 + lane, src + 128 + 40*q + 32 + lane);
}

// ---------------------------------------------------------------------------
// Main kernel: 8 warps; warp (q,slot) -> 32 channels of row pairs.
// ---------------------------------------------------------------------------
__global__ __launch_bounds__(256)
void tp_kernel(const float* __restrict__ X1, const float* __restrict__ X2,
               const float* __restrict__ W, float* __restrict__ OUT, int Z,
               Coefs coef)
{
  __shared__ float4 buf[8][2][2][72];  // [warp][dbuf][rowAB][72 float4]

  int tid  = threadIdx.x;
  int wid  = tid >> 5;
  int lane = tid & 31;
  int q    = wid & 3;
  int slot = wid >> 2;
  int blk  = blockIdx.x * 16 + 2*slot;
  int u    = q * 32 + lane;

  // hoisted weights (amortized over 8 rows)
  float wv0  = W[          u];
  float wv1  = W[ 128 +    u];
  float wv2  = W[ 256 +    u];
  float wv3  = W[ 384 +    u];
  float wv4  = W[ 512 +    u];
  float wv5  = W[ 640 +    u];
  float wv6  = W[ 768 +    u];
  float wv7  = W[ 896 +    u];
  float wv8  = W[1024 +    u];
  float wv9  = W[1152 +    u];
  float wv10 = W[1280 +    u];

  // prologue: stage pair 0
  u64 yv[9];
  {
    int rA = blk;
    if (rA < Z)     issue_slice(buf[wid][0][0], (const float4*)(X1 + (size_t)rA * 1152), q, lane);
    if (rA + 1 < Z) issue_slice(buf[wid][0][1], (const float4*)(X1 + (size_t)(rA+1) * 1152), q, lane);
    const float* ya = X2 + (size_t)rA * 9;
    const float* yb = X2 + (size_t)(rA+1) * 9;
    bool okA = rA < Z, okB = rA + 1 < Z;
    #pragma unroll
    for (int i = 0; i < 9; ++i)
      yv[i] = pack2(okA ? ya[i] : 0.0f, okB ? yb[i] : 0.0f);
  }
  asm volatile("cp.async.commit_group;");

  #pragma unroll
  for (int it = 0; it < 4; ++it) {
    int rA = blk + 4*it;
    float4 (*cur)[72] = buf[wid][it & 1];

    u64 yn[9];
    if (it < 3) {
      int nA = blk + 4*(it+1);
      if (nA < Z)     issue_slice(buf[wid][(it+1)&1][0], (const float4*)(X1 + (size_t)nA * 1152), q, lane);
      if (nA + 1 < Z) issue_slice(buf[wid][(it+1)&1][1], (const float4*)(X1 + (size_t)(nA+1) * 1152), q, lane);
      const float* ya = X2 + (size_t)nA * 9;
      const float* yb = X2 + (size_t)(nA+1) * 9;
      bool okA = nA < Z, okB = nA + 1 < Z;
      #pragma unroll
      for (int i = 0; i < 9; ++i)
        yn[i] = pack2(okA ? ya[i] : 0.0f, okB ? yb[i] : 0.0f);
    }
    asm volatile("cp.async.commit_group;");
    if (it < 3) asm volatile("cp.async.wait_group 1;");
    else        asm volatile("cp.async.wait_group 0;");
    __syncwarp();

    if (rA < Z) {
      float* sa = (float*)cur[0];
      float* sbp = (float*)cur[1];

      // gather packed x1 components (conflict-free strided LDS, 2 rows)
      u64 P0 = pack2(sa[lane],              sbp[lane]);
      u64 P1 = pack2(sa[32 + 3*lane],       sbp[32 + 3*lane]);
      u64 P2 = pack2(sa[32 + 3*lane + 1],   sbp[32 + 3*lane + 1]);
      u64 P3 = pack2(sa[32 + 3*lane + 2],   sbp[32 + 3*lane + 2]);
      u64 P4 = pack2(sa[128 + 5*lane],      sbp[128 + 5*lane]);
      u64 P5 = pack2(sa[128 + 5*lane + 1],  sbp[128 + 5*lane + 1]);
      u64 P6 = pack2(sa[128 + 5*lane + 2],  sbp[128 + 5*lane + 2]);
      u64 P7 = pack2(sa[128 + 5*lane + 3],  sbp[128 + 5*lane + 3]);
      u64 P8 = pack2(sa[128 + 5*lane + 4],  sbp[128 + 5*lane + 4]);

      u64 o0=0,o1=0,o2=0,o3=0,o4=0,o5=0,o6=0,o7=0,o8=0;

#define ACC(e,i,A,k) o##k = fma2(mul2(bcast2(coef.c[e]), P##i), A, o##k);
      { // t0
        u64 a0 = mul2(bcast2(wv0), yv[0]);
        ACC(0, 0, a0, 0)
      }
      { // t1
        u64 w1 = bcast2(wv1);
        u64 a1 = mul2(w1, yv[1]), a2 = mul2(w1, yv[2]), a3 = mul2(w1, yv[3]);
        ACC(1, 0, a1, 1)  ACC(2, 0, a2, 2)  ACC(3, 0, a3, 3)
      }
      { // t2
        u64 w2 = bcast2(wv2);
        u64 a4 = mul2(w2, yv[4]), a5 = mul2(w2, yv[5]), a6 = mul2(w2, yv[6]);
        u64 a7 = mul2(w2, yv[7]), a8 = mul2(w2, yv[8]);
        ACC(4, 0, a4, 4)  ACC(5, 0, a5, 5)  ACC(6, 0, a6, 6)  ACC(7, 0, a7, 7)  ACC(8, 0, a8, 8)
      }
      { // t3
        u64 a0 = mul2(bcast2(wv3), yv[0]);
        ACC(9, 1, a0, 1)  ACC(10, 2, a0, 2)  ACC(11, 3, a0, 3)
      }
      { // t4
        u64 w4 = bcast2(wv4);
        u64 a1 = mul2(w4, yv[1]), a2 = mul2(w4, yv[2]), a3 = mul2(w4, yv[3]);
        ACC(12, 1, a1, 0) ACC(13, 2, a2, 0) ACC(14, 3, a3, 0)
      }
      { // t5
        u64 w5 = bcast2(wv5);
        u64 a1 = mul2(w5, yv[1]), a2 = mul2(w5, yv[2]), a3 = mul2(w5, yv[3]);
        ACC(15, 2, a2, 6) ACC(16, 2, a3, 7) ACC(17, 2, a1, 5) ACC(18, 3, a2, 7)
        ACC(19, 1, a2, 5) ACC(20, 3, a3, 6) ACC(21, 1, a1, 6) ACC(22, 3, a3, 8)
        ACC(23, 1, a1, 8) ACC(24, 3, a1, 4) ACC(25, 1, a3, 4)
      }
      { // t6
        u64 w6 = bcast2(wv6);
        u64 a4 = mul2(w6, yv[4]), a5 = mul2(w6, yv[5]), a6 = mul2(w6, yv[6]);
        u64 a7 = mul2(w6, yv[7]), a8 = mul2(w6, yv[8]);
        ACC(26, 2, a6, 2) ACC(27, 2, a7, 3) ACC(28, 2, a5, 1) ACC(29, 3, a6, 3)
        ACC(30, 1, a6, 1) ACC(31, 3, a7, 2) ACC(32, 1, a5, 2) ACC(33, 3, a8, 3)
        ACC(34, 1, a8, 1) ACC(35, 3, a4, 1) ACC(36, 1, a4, 3)
      }
      { // t7
        u64 a0 = mul2(bcast2(wv7), yv[0]);
        ACC(37, 4, a0, 4) ACC(38, 5, a0, 5) ACC(39, 6, a0, 6) ACC(40, 7, a0, 7) ACC(41, 8, a0, 8)
      }
      { // t8
        u64 w8 = bcast2(wv8);
        u64 a1 = mul2(w8, yv[1]), a2 = mul2(w8, yv[2]), a3 = mul2(w8, yv[3]);
        ACC(42, 6, a2, 2) ACC(43, 6, a3, 3) ACC(44, 6, a1, 1) ACC(45, 7, a2, 3)
        ACC(46, 5, a2, 1) ACC(47, 7, a3, 2) ACC(48, 5, a1, 2) ACC(49, 8, a3, 3)
        ACC(50, 8, a1, 1) ACC(51, 4, a3, 1) ACC(52, 4, a1, 3)
      }
      { // t9
        u64 w9 = bcast2(wv9);
        u64 a4 = mul2(w9, yv[4]), a5 = mul2(w9, yv[5]), a6 = mul2(w9, yv[6]);
        u64 a7 = mul2(w9, yv[7]), a8 = mul2(w9, yv[8]);
        ACC(53, 4, a4, 0) ACC(54, 5, a5, 0) ACC(55, 6, a6, 0) ACC(56, 7, a7, 0) ACC(57, 8, a8, 0)
      }
      { // t10
        u64 w10 = bcast2(wv10);
        u64 a4 = mul2(w10, yv[4]), a5 = mul2(w10, yv[5]), a6 = mul2(w10, yv[6]);
        u64 a7 = mul2(w10, yv[7]), a8 = mul2(w10, yv[8]);
        ACC(58, 6, a6, 6) ACC(59, 6, a7, 7) ACC(60, 6, a5, 5) ACC(61, 7, a6, 7)
        ACC(62, 5, a6, 5) ACC(63, 6, a8, 8) ACC(64, 6, a4, 4) ACC(65, 8, a6, 8)
        ACC(66, 4, a6, 4) ACC(67, 7, a7, 6) ACC(68, 5, a5, 6) ACC(69, 7, a7, 8)
        ACC(70, 5, a5, 8) ACC(71, 7, a5, 4) ACC(72, 5, a7, 4) ACC(73, 7, a8, 7)
        ACC(74, 5, a8, 5) ACC(75, 7, a4, 5) ACC(76, 5, a4, 7) ACC(77, 8, a7, 7)
        ACC(78, 4, a7, 5) ACC(79, 8, a5, 5) ACC(80, 4, a5, 7) ACC(81, 8, a8, 6)
        ACC(82, 4, a4, 6)
      }
#undef ACC

      // unpack + scatter both rows into smem
      float aL, bL;
      unpack2(o0, aL, bL); sa[lane] = aL;               sbp[lane] = bL;
      unpack2(o1, aL, bL); sa[32 + 3*lane] = aL;        sbp[32 + 3*lane] = bL;
      unpack2(o2, aL, bL); sa[32 + 3*lane + 1] = aL;    sbp[32 + 3*lane + 1] = bL;
      unpack2(o3, aL, bL); sa[32 + 3*lane + 2] = aL;    sbp[32 + 3*lane + 2] = bL;
      unpack2(o4, aL, bL); sa[128 + 5*lane] = aL;       sbp[128 + 5*lane] = bL;
      unpack2(o5, aL, bL); sa[128 + 5*lane + 1] = aL;   sbp[128 + 5*lane + 1] = bL;
      unpack2(o6, aL, bL); sa[128 + 5*lane + 2] = aL;   sbp[128 + 5*lane + 2] = bL;
      unpack2(o7, aL, bL); sa[128 + 5*lane + 3] = aL;   sbp[128 + 5*lane + 3] = bL;
      unpack2(o8, aL, bL); sa[128 + 5*lane + 4] = aL;   sbp[128 + 5*lane + 4] = bL;
      __syncwarp();

      // drain both rows: smem float4 -> global float4
      {
        float4* __restrict__ dst = (float4*)(OUT + (size_t)rA * 1152);
        float4* s4 = cur[0];
        if (lane < 8)  dst[8*q + lane]             = s4[lane];
        if (lane < 24) dst[32 + 24*q + lane]       = s4[8 + lane];
        dst[128 + 40*q + lane]                     = s4[32 + lane];
        if (lane < 8)  dst[128 + 40*q + 32 + lane] = s4[64 + lane];
      }
      if (rA + 1 < Z) {
        float4* __restrict__ dst = (float4*)(OUT + (size_t)(rA+1) * 1152);
        float4* s4 = cur[1];
        if (lane < 8)  dst[8*q + lane]             = s4[lane];
        if (lane < 24) dst[32 + 24*q + lane]       = s4[8 + lane];
        dst[128 + 40*q + lane]                     = s4[32 + lane];
        if (lane < 8)  dst[128 + 40*q + 32 + lane] = s4[64 + lane];
      }
    }
    __syncwarp();

    if (it < 3) {
      #pragma unroll
      for (int i = 0; i < 9; ++i) yv[i] = yn[i];
    }
  }
}

// ---------------------------------------------------------------------------
extern "C" void kernel_launch(void* const* d_in, const int* in_sizes, int n_in,
                              void* d_out, int out_size)
{
  const float* x1 = (const float*)d_in[0];
  const float* x2 = (const float*)d_in[1];
  const float* w  = (const float*)d_in[2];
  if (n_in >= 3) {
    int iw = -1, imax = -1;
    long long smax = -1;
    for (int i = 0; i < 3; ++i) {
      if (in_sizes[i] == 1408) iw = i;
      if ((long long)in_sizes[i] > smax) { smax = in_sizes[i]; imax = i; }
    }
    if (iw >= 0 && imax >= 0 && iw != imax) {
      int ix2 = 3 - iw - imax;
      x1 = (const float*)d_in[imax];
      x2 = (const float*)d_in[ix2];
      w  = (const float*)d_in[iw];
    }
  }

  int Z = in_sizes[0] > in_sizes[1]
            ? (in_sizes[0] > in_sizes[2] ? in_sizes[0] : in_sizes[2])
            : (in_sizes[1] > in_sizes[2] ? in_sizes[1] : in_sizes[2]);
  Z /= 1152;

  Coefs coef;
  compute_coefs(&coef);

  int grid = (Z + 15) / 16;
  tp_kernel<<<grid, 256>>>(x1, x2, w, (float*)d_out, Z, coef);
}

// round 10
// speedup vs baseline: 1.0559x; 1.0559x over previous
#include <cuda_runtime.h>
#include <math.h>

// ============================================================================
// Sparse e3nn tensor product, uvu mode — f32x2 row-pair, register-budgeted.
// irreps1 = 128x0e+128x1o+128x2e (x1: [Z,1152]), irreps2 = 1x0e+1x1o+1x2e.
// 83-entry hardcoded sparsity; coefficients computed on HOST (fp64), passed
// by value (constant bank / LDCU). Each warp: 32 channels x 2 rows per iter,
// 4 iters, double-buffered cp.async, lazy packed operands, no block barriers.
// ============================================================================

#define NE 83
#define NT 11

struct Coefs { float c[NE]; };

// ---------------- host-side tables (sparsity pattern) ----------------------
static const int hTL1[NT] = {0,0,0,1,1,1,1,2,2,2,2};
static const int hTL2[NT] = {0,1,2,0,1,1,2,0,1,2,2};
static const int hTL3[NT] = {0,1,2,1,0,2,1,2,1,0,2};
static const double hTALPHA[NT] = {
  0.5773502691896258, 0.8660254037844386, 1.1180339887498949,
  0.8660254037844386, 0.5773502691896258, 1.1180339887498949,
  0.8660254037844386, 1.1180339887498949, 0.8660254037844386,
  0.5773502691896258, 1.1180339887498949};

static const unsigned char hENT_T[NE] = {
  0, 1,1,1, 2,2,2,2,2, 3,3,3, 4,4,4,
  5,5,5,5,5,5,5,5,5,5,5,
  6,6,6,6,6,6,6,6,6,6,6,
  7,7,7,7,7,
  8,8,8,8,8,8,8,8,8,8,8,
  9,9,9,9,9,
  10,10,10,10,10,10,10,10,10,10,10,10,10,10,10,10,10,10,10,10,10,10,10,10,10};
static const unsigned char hENT_I[NE] = {
  0, 0,0,0, 0,0,0,0,0, 0,1,2, 0,1,2,
  1,1,1,2,0,2,0,2,0,2,0,
  1,1,1,2,0,2,0,2,0,2,0,
  0,1,2,3,4,
  2,2,2,3,1,3,1,4,4,0,0,
  0,1,2,3,4,
  2,2,2,3,1,2,2,4,0,3,1,3,1,3,1,3,1,3,1,4,0,4,0,4,0};
static const unsigned char hENT_J[NE] = {
  0, 0,1,2, 0,1,2,3,4, 0,0,0, 0,1,2,
  1,2,0,1,1,2,0,2,0,0,2,
  2,3,1,2,2,3,1,4,4,0,0,
  0,0,0,0,0,
  1,2,0,1,1,2,0,2,0,2,0,
  0,1,2,3,4,
  2,3,1,2,2,4,0,2,2,3,1,3,1,1,3,4,4,0,0,3,3,1,1,4,0};
static const unsigned char hENT_K[NE] = {
  0, 0,1,2, 0,1,2,3,4, 0,1,2, 0,0,0,
  2,3,1,3,1,2,2,4,4,0,0,
  1,2,0,2,0,1,1,2,0,0,2,
  0,1,2,3,4,
  1,2,0,2,0,1,1,2,0,0,2,
  0,0,0,0,0,
  2,3,1,3,1,4,0,4,0,2,2,4,4,0,0,3,1,1,3,3,1,1,3,2,2};

// ---------------- host coefficient computation (fp64) ----------------------
static double hfact(int n) {
  double r = 1.0;
  for (int i = 2; i <= n; ++i) r *= (double)i;
  return r;
}

static double hsu2cg(int j1,int m1,int j2,int m2,int j3,int m3) {
  if (m1 + m2 != m3) return 0.0;
  int vmin = -j1+j2+m3; if (-j1+m1 > vmin) vmin = -j1+m1; if (vmin < 0) vmin = 0;
  int vmax = j2+j3+m1; if (j3-j1+j2 < vmax) vmax = j3-j1+j2; if (j3+m3 < vmax) vmax = j3+m3;
  double C = sqrt((2.0*j3+1.0)*hfact(j3+j1-j2)*hfact(j3-j1+j2)*hfact(j1+j2-j3)
                  *hfact(j3+m3)*hfact(j3-m3)
                  /(hfact(j1+j2+j3+1)*hfact(j1-m1)*hfact(j1+m1)*hfact(j2-m2)*hfact(j2+m2)));
  double S = 0.0;
  for (int v = vmin; v <= vmax; ++v) {
    double s = ((v + j2 + m2) & 1) ? -1.0 : 1.0;
    S += s * hfact(j2+j3+m1-v)*hfact(j1-m1+v)
         /(hfact(v)*hfact(j3-j1+j2-v)*hfact(j3+m3-v)*hfact(v+j1-j2-m3));
  }
  return C * S;
}

static void hqent(int l, int r, int c, double* qr, double* qi) {
  const double inv2 = 0.7071067811865476;
  double re = 0.0, im = 0.0;
  int m = r - l;
  if (m < 0) {
    if (c == l - m) re = inv2;
    if (c == l + m) im = -inv2;
  } else if (m == 0) {
    if (c == l) re = 1.0;
  } else {
    double s = (m & 1) ? -1.0 : 1.0;
    if (c == l + m) re = s * inv2;
    if (c == l - m) im = s * inv2;
  }
  if (l == 1) { double t0 = re; re = im; im = -t0; }
  else if (l == 2) { re = -re; im = -im; }
  *qr = re; *qi = im;
}

static void compute_coefs(Coefs* out) {
  for (int t = 0; t < NT; ++t) {
    int l1 = hTL1[t], l2 = hTL2[t], l3 = hTL3[t];
    int d1 = 2*l1+1, d2 = 2*l2+1, d3 = 2*l3+1;
    double cgc[125], cre[125];
    for (int i = 0; i < d1; ++i)
      for (int k = 0; k < d2; ++k)
        for (int nn = 0; nn < d3; ++nn)
          cgc[(i*d2+k)*d3+nn] = hsu2cg(l1, i-l1, l2, k-l2, l3, nn-l3);
    double nrm = 0.0;
    for (int j = 0; j < d1; ++j)
      for (int l = 0; l < d2; ++l)
        for (int m = 0; m < d3; ++m) {
          double acc = 0.0;
          for (int i = 0; i < d1; ++i)
            for (int k = 0; k < d2; ++k) {
              int nn = (i-l1) + (k-l2) + l3;
              if (nn < 0 || nn >= d3) continue;
              double cv = cgc[(i*d2+k)*d3+nn];
              if (cv == 0.0) continue;
              double q1r,q1i,q2r,q2i,q3r,q3i;
              hqent(l1, i,  j, &q1r, &q1i);
              if (q1r == 0.0 && q1i == 0.0) continue;
              hqent(l2, k,  l, &q2r, &q2i);
              if (q2r == 0.0 && q2i == 0.0) continue;
              hqent(l3, nn, m, &q3r, &q3i);
              double tr = q1r*q2r - q1i*q2i;
              double ti = q1r*q2i + q1i*q2r;
              acc += cv * (tr*q3r + ti*q3i);
            }
          cre[(j*d2+l)*d3+m] = acc;
          nrm += acc*acc;
        }
    double scale = hTALPHA[t] / sqrt(nrm);
    for (int e = 0; e < NE; ++e) {
      if (hENT_T[e] != t) continue;
      int idx = ((int)hENT_I[e]*d2 + (int)hENT_J[e])*d3 + (int)hENT_K[e];
      out->c[e] = (float)(cre[idx] * scale);
    }
  }
}

// ---------------------------------------------------------------------------
// Device helpers
// ---------------------------------------------------------------------------
typedef unsigned long long u64;

__device__ __forceinline__ u64 pack2(float lo, float hi) {
  u64 r; asm("mov.b64 %0, {%1, %2};" : "=l"(r) : "f"(lo), "f"(hi)); return r;
}
__device__ __forceinline__ u64 bcast2(float v) {
  u64 r; asm("mov.b64 %0, {%1, %1};" : "=l"(r) : "f"(v)); return r;
}
__device__ __forceinline__ void unpack2(u64 v, float& lo, float& hi) {
  asm("mov.b64 {%0, %1}, %2;" : "=f"(lo), "=f"(hi) : "l"(v));
}
__device__ __forceinline__ u64 mul2(u64 a, u64 b) {
  u64 r; asm("mul.rn.f32x2 %0, %1, %2;" : "=l"(r) : "l"(a), "l"(b)); return r;
}
__device__ __forceinline__ u64 fma2(u64 a, u64 b, u64 c) {
  u64 r; asm("fma.rn.f32x2 %0, %1, %2, %3;" : "=l"(r) : "l"(a), "l"(b), "l"(c)); return r;
}

#define CPA16(dst, src) \
  asm volatile("cp.async.cg.shared.global [%0], [%1], 16;" :: \
               "r"((unsigned)__cvta_generic_to_shared(dst)), "l"(src))

__device__ __forceinline__ void issue_slice(float4* sb4, const float4* src,
                                            int q, int lane) {
  if (lane < 8)  CPA16(sb4 + lane,      src + 8*q + lane);
  if (lane < 24) CPA16(sb4 + 8 + lane,  src + 32 + 24*q + lane);
  CPA16(sb4 + 32 + lane, src + 128 + 40*q + lane);
  if (lane < 8)  CPA16(sb4 + 64 + lane, src + 128 + 40*q + 32 + lane);
}

// ---------------------------------------------------------------------------
// Main kernel
// ---------------------------------------------------------------------------
__global__ __launch_bounds__(256, 3)
void tp_kernel(const float* __restrict__ X1, const float* __restrict__ X2,
               const float* __restrict__ W, float* __restrict__ OUT, int Z,
               Coefs coef)
{
  __shared__ float4 buf[8][2][2][72];  // [warp][dbuf][rowAB][72 float4]

  int tid  = threadIdx.x;
  int wid  = tid >> 5;
  int lane = tid & 31;
  int q    = wid & 3;
  int slot = wid >> 2;
  int blk  = blockIdx.x * 16 + 2*slot;
  int u    = q * 32 + lane;

  // hoisted weights (amortized over 8 rows)
  float wv0  = W[          u];
  float wv1  = W[ 128 +    u];
  float wv2  = W[ 256 +    u];
  float wv3  = W[ 384 +    u];
  float wv4  = W[ 512 +    u];
  float wv5  = W[ 640 +    u];
  float wv6  = W[ 768 +    u];
  float wv7  = W[ 896 +    u];
  float wv8  = W[1024 +    u];
  float wv9  = W[1152 +    u];
  float wv10 = W[1280 +    u];

  // prologue: stage pair 0
  {
    int rA = blk;
    if (rA < Z)     issue_slice(buf[wid][0][0], (const float4*)(X1 + (size_t)rA * 1152), q, lane);
    if (rA + 1 < Z) issue_slice(buf[wid][0][1], (const float4*)(X1 + (size_t)(rA+1) * 1152), q, lane);
  }
  asm volatile("cp.async.commit_group;");

  #pragma unroll
  for (int it = 0; it < 4; ++it) {
    int rA = blk + 4*it;
    float4 (*cur)[72] = buf[wid][it & 1];

    if (it < 3) {
      int nA = blk + 4*(it+1);
      if (nA < Z)     issue_slice(buf[wid][(it+1)&1][0], (const float4*)(X1 + (size_t)nA * 1152), q, lane);
      if (nA + 1 < Z) issue_slice(buf[wid][(it+1)&1][1], (const float4*)(X1 + (size_t)(nA+1) * 1152), q, lane);
    }
    asm volatile("cp.async.commit_group;");
    if (it < 3) asm volatile("cp.async.wait_group 1;");
    else        asm volatile("cp.async.wait_group 0;");
    __syncwarp();

    if (rA < Z) {
      float* sa  = (float*)cur[0];
      float* sbp = (float*)cur[1];
      bool okB = (rA + 1 < Z);
      const float* ya = X2 + (size_t)rA * 9;
      const float* yb = X2 + (size_t)(rA+1) * 9;

      // lazy packed y (L1-hit LDGs, packed on ALU pipe)
      #define YPK(j) pack2(ya[j], okB ? yb[j] : 0.0f)

      u64 o0=0,o1=0,o2=0,o3=0,o4=0,o5=0,o6=0,o7=0,o8=0;

#define ACC2(e,P,A,k) o##k = fma2(mul2(bcast2(coef.c[e]), P), A, o##k);

      u64 Y0 = YPK(0), Y1 = YPK(1), Y2 = YPK(2), Y3 = YPK(3), Y4 = YPK(4);
      u64 Y5 = YPK(5), Y6 = YPK(6), Y7 = YPK(7), Y8 = YPK(8);

      // ---- phase 1: P0 (l=0 input) ----
      {
        u64 P0 = pack2(sa[lane], sbp[lane]);
        { // t0
          u64 a0 = mul2(bcast2(wv0), Y0);
          ACC2(0, P0, a0, 0)
        }
        { // t1
          u64 w1 = bcast2(wv1);
          u64 a1 = mul2(w1, Y1), a2 = mul2(w1, Y2), a3 = mul2(w1, Y3);
          ACC2(1, P0, a1, 1)  ACC2(2, P0, a2, 2)  ACC2(3, P0, a3, 3)
        }
        { // t2
          u64 w2 = bcast2(wv2);
          u64 a4 = mul2(w2, Y4), a5 = mul2(w2, Y5), a6 = mul2(w2, Y6);
          u64 a7 = mul2(w2, Y7), a8 = mul2(w2, Y8);
          ACC2(4, P0, a4, 4)  ACC2(5, P0, a5, 5)  ACC2(6, P0, a6, 6)
          ACC2(7, P0, a7, 7)  ACC2(8, P0, a8, 8)
        }
      }

      // ---- phase 2: P1..P3 (l=1 input) ----
      {
        u64 P1 = pack2(sa[32 + 3*lane    ], sbp[32 + 3*lane    ]);
        u64 P2 = pack2(sa[32 + 3*lane + 1], sbp[32 + 3*lane + 1]);
        u64 P3 = pack2(sa[32 + 3*lane + 2], sbp[32 + 3*lane + 2]);
        { // t3
          u64 a0 = mul2(bcast2(wv3), Y0);
          ACC2(9, P1, a0, 1)  ACC2(10, P2, a0, 2)  ACC2(11, P3, a0, 3)
        }
        { // t4
          u64 w4 = bcast2(wv4);
          u64 a1 = mul2(w4, Y1), a2 = mul2(w4, Y2), a3 = mul2(w4, Y3);
          ACC2(12, P1, a1, 0) ACC2(13, P2, a2, 0) ACC2(14, P3, a3, 0)
        }
        { // t5
          u64 w5 = bcast2(wv5);
          u64 a1 = mul2(w5, Y1), a2 = mul2(w5, Y2), a3 = mul2(w5, Y3);
          ACC2(15, P2, a2, 6) ACC2(16, P2, a3, 7) ACC2(17, P2, a1, 5) ACC2(18, P3, a2, 7)
          ACC2(19, P1, a2, 5) ACC2(20, P3, a3, 6) ACC2(21, P1, a1, 6) ACC2(22, P3, a3, 8)
          ACC2(23, P1, a1, 8) ACC2(24, P3, a1, 4) ACC2(25, P1, a3, 4)
        }
        { // t6
          u64 w6 = bcast2(wv6);
          u64 a4 = mul2(w6, Y4), a5 = mul2(w6, Y5), a6 = mul2(w6, Y6);
          u64 a7 = mul2(w6, Y7), a8 = mul2(w6, Y8);
          ACC2(26, P2, a6, 2) ACC2(27, P2, a7, 3) ACC2(28, P2, a5, 1) ACC2(29, P3, a6, 3)
          ACC2(30, P1, a6, 1) ACC2(31, P3, a7, 2) ACC2(32, P1, a5, 2) ACC2(33, P3, a8, 3)
          ACC2(34, P1, a8, 1) ACC2(35, P3, a4, 1) ACC2(36, P1, a4, 3)
        }
      }

      // ---- phase 3: P4..P8 (l=2 input) ----
      {
        u64 P4 = pack2(sa[128 + 5*lane    ], sbp[128 + 5*lane    ]);
        u64 P5 = pack2(sa[128 + 5*lane + 1], sbp[128 + 5*lane + 1]);
        u64 P6 = pack2(sa[128 + 5*lane + 2], sbp[128 + 5*lane + 2]);
        u64 P7 = pack2(sa[128 + 5*lane + 3], sbp[128 + 5*lane + 3]);
        u64 P8 = pack2(sa[128 + 5*lane + 4], sbp[128 + 5*lane + 4]);
        { // t7
          u64 a0 = mul2(bcast2(wv7), Y0);
          ACC2(37, P4, a0, 4) ACC2(38, P5, a0, 5) ACC2(39, P6, a0, 6)
          ACC2(40, P7, a0, 7) ACC2(41, P8, a0, 8)
        }
        { // t8
          u64 w8 = bcast2(wv8);
          u64 a1 = mul2(w8, Y1), a2 = mul2(w8, Y2), a3 = mul2(w8, Y3);
          ACC2(42, P6, a2, 2) ACC2(43, P6, a3, 3) ACC2(44, P6, a1, 1) ACC2(45, P7, a2, 3)
          ACC2(46, P5, a2, 1) ACC2(47, P7, a3, 2) ACC2(48, P5, a1, 2) ACC2(49, P8, a3, 3)
          ACC2(50, P8, a1, 1) ACC2(51, P4, a3, 1) ACC2(52, P4, a1, 3)
        }
        { // t9
          u64 w9 = bcast2(wv9);
          u64 a4 = mul2(w9, Y4), a5 = mul2(w9, Y5), a6 = mul2(w9, Y6);
          u64 a7 = mul2(w9, Y7), a8 = mul2(w9, Y8);
          ACC2(53, P4, a4, 0) ACC2(54, P5, a5, 0) ACC2(55, P6, a6, 0)
          ACC2(56, P7, a7, 0) ACC2(57, P8, a8, 0)
        }
        { // t10
          u64 w10 = bcast2(wv10);
          u64 a4 = mul2(w10, Y4), a5 = mul2(w10, Y5), a6 = mul2(w10, Y6);
          u64 a7 = mul2(w10, Y7), a8 = mul2(w10, Y8);
          ACC2(58, P6, a6, 6) ACC2(59, P6, a7, 7) ACC2(60, P6, a5, 5) ACC2(61, P7, a6, 7)
          ACC2(62, P5, a6, 5) ACC2(63, P6, a8, 8) ACC2(64, P6, a4, 4) ACC2(65, P8, a6, 8)
          ACC2(66, P4, a6, 4) ACC2(67, P7, a7, 6) ACC2(68, P5, a5, 6) ACC2(69, P7, a7, 8)
          ACC2(70, P5, a5, 8) ACC2(71, P7, a5, 4) ACC2(72, P5, a7, 4) ACC2(73, P7, a8, 7)
          ACC2(74, P5, a8, 5) ACC2(75, P7, a4, 5) ACC2(76, P5, a4, 7) ACC2(77, P8, a7, 7)
          ACC2(78, P4, a7, 5) ACC2(79, P8, a5, 5) ACC2(80, P4, a5, 7) ACC2(81, P8, a8, 6)
          ACC2(82, P4, a4, 6)
        }
      }
#undef ACC2
#undef YPK

      // unpack + scatter both rows into smem
      float aL, bL;
      unpack2(o0, aL, bL); sa[lane] = aL;               sbp[lane] = bL;
      unpack2(o1, aL, bL); sa[32 + 3*lane] = aL;        sbp[32 + 3*lane] = bL;
      unpack2(o2, aL, bL); sa[32 + 3*lane + 1] = aL;    sbp[32 + 3*lane + 1] = bL;
      unpack2(o3, aL, bL); sa[32 + 3*lane + 2] = aL;    sbp[32 + 3*lane + 2] = bL;
      unpack2(o4, aL, bL); sa[128 + 5*lane] = aL;       sbp[128 + 5*lane] = bL;
      unpack2(o5, aL, bL); sa[128 + 5*lane + 1] = aL;   sbp[128 + 5*lane + 1] = bL;
      unpack2(o6, aL, bL); sa[128 + 5*lane + 2] = aL;   sbp[128 + 5*lane + 2] = bL;
      unpack2(o7, aL, bL); sa[128 + 5*lane + 3] = aL;   sbp[128 + 5*lane + 3] = bL;
      unpack2(o8, aL, bL); sa[128 + 5*lane + 4] = aL;   sbp[128 + 5*lane + 4] = bL;
      __syncwarp();

      // drain both rows: smem float4 -> global float4
      {
        float4* __restrict__ dst = (float4*)(OUT + (size_t)rA * 1152);
        float4* s4 = cur[0];
        if (lane < 8)  dst[8*q + lane]             = s4[lane];
        if (lane < 24) dst[32 + 24*q + lane]       = s4[8 + lane];
        dst[128 + 40*q + lane]                     = s4[32 + lane];
        if (lane < 8)  dst[128 + 40*q + 32 + lane] = s4[64 + lane];
      }
      if (okB) {
        float4* __restrict__ dst = (float4*)(OUT + (size_t)(rA+1) * 1152);
        float4* s4 = cur[1];
        if (lane < 8)  dst[8*q + lane]             = s4[lane];
        if (lane < 24) dst[32 + 24*q + lane]       = s4[8 + lane];
        dst[128 + 40*q + lane]                     = s4[32 + lane];
        if (lane < 8)  dst[128 + 40*q + 32 + lane] = s4[64 + lane];
      }
    }
    __syncwarp();
  }
}

// ---------------------------------------------------------------------------
extern "C" void kernel_launch(void* const* d_in, const int* in_sizes, int n_in,
                              void* d_out, int out_size)
{
  const float* x1 = (const float*)d_in[0];
  const float* x2 = (const float*)d_in[1];
  const float* w  = (const float*)d_in[2];
  if (n_in >= 3) {
    int iw = -1, imax = -1;
    long long smax = -1;
    for (int i = 0; i < 3; ++i) {
      if (in_sizes[i] == 1408) iw = i;
      if ((long long)in_sizes[i] > smax) { smax = in_sizes[i]; imax = i; }
    }
    if (iw >= 0 && imax >= 0 && iw != imax) {
      int ix2 = 3 - iw - imax;
      x1 = (const float*)d_in[imax];
      x2 = (const float*)d_in[ix2];
      w  = (const float*)d_in[iw];
    }
  }

  int Z = in_sizes[0] > in_sizes[1]
            ? (in_sizes[0] > in_sizes[2] ? in_sizes[0] : in_sizes[2])
            : (in_sizes[1] > in_sizes[2] ? in_sizes[1] : in_sizes[2]);
  Z /= 1152;

  Coefs coef;
  compute_coefs(&coef);

  int grid = (Z + 15) / 16;
  tp_kernel<<<grid, 256>>>(x1, x2, w, (float*)d_out, Z, coef);
}

// round 11
// speedup vs baseline: 1.0994x; 1.0411x over previous
#include <cuda_runtime.h>
#include <math.h>

// ============================================================================
// Sparse e3nn tensor product, uvu mode — f32x2 row-pair, 4-blocks/SM budget.
// irreps1 = 128x0e+128x1o+128x2e (x1: [Z,1152]), irreps2 = 1x0e+1x1o+1x2e.
// 83-entry hardcoded sparsity; coefficients computed on HOST (fp64), passed
// by value. Each warp: 32 channels x 2 rows per iter, 4 iters, double-
// buffered cp.async, lazy weights/y/P packing, no block barriers.
// ============================================================================

#define NE 83
#define NT 11

struct Coefs { float c[NE]; };

// ---------------- host-side tables (sparsity pattern) ----------------------
static const int hTL1[NT] = {0,0,0,1,1,1,1,2,2,2,2};
static const int hTL2[NT] = {0,1,2,0,1,1,2,0,1,2,2};
static const int hTL3[NT] = {0,1,2,1,0,2,1,2,1,0,2};
static const double hTALPHA[NT] = {
  0.5773502691896258, 0.8660254037844386, 1.1180339887498949,
  0.8660254037844386, 0.5773502691896258, 1.1180339887498949,
  0.8660254037844386, 1.1180339887498949, 0.8660254037844386,
  0.5773502691896258, 1.1180339887498949};

static const unsigned char hENT_T[NE] = {
  0, 1,1,1, 2,2,2,2,2, 3,3,3, 4,4,4,
  5,5,5,5,5,5,5,5,5,5,5,
  6,6,6,6,6,6,6,6,6,6,6,
  7,7,7,7,7,
  8,8,8,8,8,8,8,8,8,8,8,
  9,9,9,9,9,
  10,10,10,10,10,10,10,10,10,10,10,10,10,10,10,10,10,10,10,10,10,10,10,10,10};
static const unsigned char hENT_I[NE] = {
  0, 0,0,0, 0,0,0,0,0, 0,1,2, 0,1,2,
  1,1,1,2,0,2,0,2,0,2,0,
  1,1,1,2,0,2,0,2,0,2,0,
  0,1,2,3,4,
  2,2,2,3,1,3,1,4,4,0,0,
  0,1,2,3,4,
  2,2,2,3,1,2,2,4,0,3,1,3,1,3,1,3,1,3,1,4,0,4,0,4,0};
static const unsigned char hENT_J[NE] = {
  0, 0,1,2, 0,1,2,3,4, 0,0,0, 0,1,2,
  1,2,0,1,1,2,0,2,0,0,2,
  2,3,1,2,2,3,1,4,4,0,0,
  0,0,0,0,0,
  1,2,0,1,1,2,0,2,0,2,0,
  0,1,2,3,4,
  2,3,1,2,2,4,0,2,2,3,1,3,1,1,3,4,4,0,0,3,3,1,1,4,0};
static const unsigned char hENT_K[NE] = {
  0, 0,1,2, 0,1,2,3,4, 0,1,2, 0,0,0,
  2,3,1,3,1,2,2,4,4,0,0,
  1,2,0,2,0,1,1,2,0,0,2,
  0,1,2,3,4,
  1,2,0,2,0,1,1,2,0,0,2,
  0,0,0,0,0,
  2,3,1,3,1,4,0,4,0,2,2,4,4,0,0,3,1,1,3,3,1,1,3,2,2};

// ---------------- host coefficient computation (fp64) ----------------------
static double hfact(int n) {
  double r = 1.0;
  for (int i = 2; i <= n; ++i) r *= (double)i;
  return r;
}

static double hsu2cg(int j1,int m1,int j2,int m2,int j3,int m3) {
  if (m1 + m2 != m3) return 0.0;
  int vmin = -j1+j2+m3; if (-j1+m1 > vmin) vmin = -j1+m1; if (vmin < 0) vmin = 0;
  int vmax = j2+j3+m1; if (j3-j1+j2 < vmax) vmax = j3-j1+j2; if (j3+m3 < vmax) vmax = j3+m3;
  double C = sqrt((2.0*j3+1.0)*hfact(j3+j1-j2)*hfact(j3-j1+j2)*hfact(j1+j2-j3)
                  *hfact(j3+m3)*hfact(j3-m3)
                  /(hfact(j1+j2+j3+1)*hfact(j1-m1)*hfact(j1+m1)*hfact(j2-m2)*hfact(j2+m2)));
  double S = 0.0;
  for (int v = vmin; v <= vmax; ++v) {
    double s = ((v + j2 + m2) & 1) ? -1.0 : 1.0;
    S += s * hfact(j2+j3+m1-v)*hfact(j1-m1+v)
         /(hfact(v)*hfact(j3-j1+j2-v)*hfact(j3+m3-v)*hfact(v+j1-j2-m3));
  }
  return C * S;
}

static void hqent(int l, int r, int c, double* qr, double* qi) {
  const double inv2 = 0.7071067811865476;
  double re = 0.0, im = 0.0;
  int m = r - l;
  if (m < 0) {
    if (c == l - m) re = inv2;
    if (c == l + m) im = -inv2;
  } else if (m == 0) {
    if (c == l) re = 1.0;
  } else {
    double s = (m & 1) ? -1.0 : 1.0;
    if (c == l + m) re = s * inv2;
    if (c == l - m) im = s * inv2;
  }
  if (l == 1) { double t0 = re; re = im; im = -t0; }
  else if (l == 2) { re = -re; im = -im; }
  *qr = re; *qi = im;
}

static void compute_coefs(Coefs* out) {
  for (int t = 0; t < NT; ++t) {
    int l1 = hTL1[t], l2 = hTL2[t], l3 = hTL3[t];
    int d1 = 2*l1+1, d2 = 2*l2+1, d3 = 2*l3+1;
    double cgc[125], cre[125];
    for (int i = 0; i < d1; ++i)
      for (int k = 0; k < d2; ++k)
        for (int nn = 0; nn < d3; ++nn)
          cgc[(i*d2+k)*d3+nn] = hsu2cg(l1, i-l1, l2, k-l2, l3, nn-l3);
    double nrm = 0.0;
    for (int j = 0; j < d1; ++j)
      for (int l = 0; l < d2; ++l)
        for (int m = 0; m < d3; ++m) {
          double acc = 0.0;
          for (int i = 0; i < d1; ++i)
            for (int k = 0; k < d2; ++k) {
              int nn = (i-l1) + (k-l2) + l3;
              if (nn < 0 || nn >= d3) continue;
              double cv = cgc[(i*d2+k)*d3+nn];
              if (cv == 0.0) continue;
              double q1r,q1i,q2r,q2i,q3r,q3i;
              hqent(l1, i,  j, &q1r, &q1i);
              if (q1r == 0.0 && q1i == 0.0) continue;
              hqent(l2, k,  l, &q2r, &q2i);
              if (q2r == 0.0 && q2i == 0.0) continue;
              hqent(l3, nn, m, &q3r, &q3i);
              double tr = q1r*q2r - q1i*q2i;
              double ti = q1r*q2i + q1i*q2r;
              acc += cv * (tr*q3r + ti*q3i);
            }
          cre[(j*d2+l)*d3+m] = acc;
          nrm += acc*acc;
        }
    double scale = hTALPHA[t] / sqrt(nrm);
    for (int e = 0; e < NE; ++e) {
      if (hENT_T[e] != t) continue;
      int idx = ((int)hENT_I[e]*d2 + (int)hENT_J[e])*d3 + (int)hENT_K[e];
      out->c[e] = (float)(cre[idx] * scale);
    }
  }
}

// ---------------------------------------------------------------------------
// Device helpers
// ---------------------------------------------------------------------------
typedef unsigned long long u64;

__device__ __forceinline__ u64 pack2(float lo, float hi) {
  u64 r; asm("mov.b64 %0, {%1, %2};" : "=l"(r) : "f"(lo), "f"(hi)); return r;
}
__device__ __forceinline__ u64 bcast2(float v) {
  u64 r; asm("mov.b64 %0, {%1, %1};" : "=l"(r) : "f"(v)); return r;
}
__device__ __forceinline__ void unpack2(u64 v, float& lo, float& hi) {
  asm("mov.b64 {%0, %1}, %2;" : "=f"(lo), "=f"(hi) : "l"(v));
}
__device__ __forceinline__ u64 mul2(u64 a, u64 b) {
  u64 r; asm("mul.rn.f32x2 %0, %1, %2;" : "=l"(r) : "l"(a), "l"(b)); return r;
}
__device__ __forceinline__ u64 fma2(u64 a, u64 b, u64 c) {
  u64 r; asm("fma.rn.f32x2 %0, %1, %2, %3;" : "=l"(r) : "l"(a), "l"(b), "l"(c)); return r;
}

#define CPA16(dst, src) \
  asm volatile("cp.async.cg.shared.global [%0], [%1], 16;" :: \
               "r"((unsigned)__cvta_generic_to_shared(dst)), "l"(src))

__device__ __forceinline__ void issue_slice(float4* sb4, const float4* src,
                                            int q, int lane) {
  if (lane < 8)  CPA16(sb4 + lane,      src + 8*q + lane);
  if (lane < 24) CPA16(sb4 + 8 + lane,  src + 32 + 24*q + lane);
  CPA16(sb4 + 32 + lane, src + 128 + 40*q + lane);
  if (lane < 8)  CPA16(sb4 + 64 + lane, src + 128 + 40*q + 32 + lane);
}

// ---------------------------------------------------------------------------
// Main kernel
// ---------------------------------------------------------------------------
__global__ __launch_bounds__(256, 4)
void tp_kernel(const float* __restrict__ X1, const float* __restrict__ X2,
               const float* __restrict__ W, float* __restrict__ OUT, int Z,
               Coefs coef)
{
  __shared__ float4 buf[8][2][2][72];  // [warp][dbuf][rowAB][72 float4]

  int tid  = threadIdx.x;
  int wid  = tid >> 5;
  int lane = tid & 31;
  int q    = wid & 3;
  int slot = wid >> 2;
  int blk  = blockIdx.x * 16 + 2*slot;
  int u    = q * 32 + lane;

  const float* __restrict__ Wu = W + u;  // lazy per-group weight loads (L1 hits)

  // prologue: stage pair 0
  {
    int rA = blk;
    if (rA < Z)     issue_slice(buf[wid][0][0], (const float4*)(X1 + (size_t)rA * 1152), q, lane);
    if (rA + 1 < Z) issue_slice(buf[wid][0][1], (const float4*)(X1 + (size_t)(rA+1) * 1152), q, lane);
  }
  asm volatile("cp.async.commit_group;");

  #pragma unroll
  for (int it = 0; it < 4; ++it) {
    int rA = blk + 4*it;
    float4 (*cur)[72] = buf[wid][it & 1];

    if (it < 3) {
      int nA = blk + 4*(it+1);
      if (nA < Z)     issue_slice(buf[wid][(it+1)&1][0], (const float4*)(X1 + (size_t)nA * 1152), q, lane);
      if (nA + 1 < Z) issue_slice(buf[wid][(it+1)&1][1], (const float4*)(X1 + (size_t)(nA+1) * 1152), q, lane);
    }
    asm volatile("cp.async.commit_group;");
    if (it < 3) asm volatile("cp.async.wait_group 1;");
    else        asm volatile("cp.async.wait_group 0;");
    __syncwarp();

    if (rA < Z) {
      float* sa  = (float*)cur[0];
      float* sbp = (float*)cur[1];
      bool okB = (rA + 1 < Z);
      const float* ya = X2 + (size_t)rA * 9;
      const float* yb = X2 + (size_t)(rA+1) * 9;

      #define YPK(j) pack2(ya[j], okB ? yb[j] : 0.0f)
      #define WB(t)  bcast2(__ldg(Wu + 128*(t)))

      u64 o0=0,o1=0,o2=0,o3=0,o4=0,o5=0,o6=0,o7=0,o8=0;

#define ACC2(e,P,A,k) o##k = fma2(mul2(bcast2(coef.c[e]), P), A, o##k);

      u64 Y0 = YPK(0), Y1 = YPK(1), Y2 = YPK(2), Y3 = YPK(3), Y4 = YPK(4);
      u64 Y5 = YPK(5), Y6 = YPK(6), Y7 = YPK(7), Y8 = YPK(8);

      // ---- phase 1: P0 (l=0 input) ----
      {
        u64 P0 = pack2(sa[lane], sbp[lane]);
        { // t0
          u64 a0 = mul2(WB(0), Y0);
          ACC2(0, P0, a0, 0)
        }
        { // t1
          u64 w1 = WB(1);
          u64 a1 = mul2(w1, Y1), a2 = mul2(w1, Y2), a3 = mul2(w1, Y3);
          ACC2(1, P0, a1, 1)  ACC2(2, P0, a2, 2)  ACC2(3, P0, a3, 3)
        }
        { // t2
          u64 w2 = WB(2);
          u64 a4 = mul2(w2, Y4), a5 = mul2(w2, Y5), a6 = mul2(w2, Y6);
          u64 a7 = mul2(w2, Y7), a8 = mul2(w2, Y8);
          ACC2(4, P0, a4, 4)  ACC2(5, P0, a5, 5)  ACC2(6, P0, a6, 6)
          ACC2(7, P0, a7, 7)  ACC2(8, P0, a8, 8)
        }
      }

      // ---- phase 2: P1..P3 (l=1 input) ----
      {
        u64 P1 = pack2(sa[32 + 3*lane    ], sbp[32 + 3*lane    ]);
        u64 P2 = pack2(sa[32 + 3*lane + 1], sbp[32 + 3*lane + 1]);
        u64 P3 = pack2(sa[32 + 3*lane + 2], sbp[32 + 3*lane + 2]);
        { // t3
          u64 a0 = mul2(WB(3), Y0);
          ACC2(9, P1, a0, 1)  ACC2(10, P2, a0, 2)  ACC2(11, P3, a0, 3)
        }
        { // t4
          u64 w4 = WB(4);
          u64 a1 = mul2(w4, Y1), a2 = mul2(w4, Y2), a3 = mul2(w4, Y3);
          ACC2(12, P1, a1, 0) ACC2(13, P2, a2, 0) ACC2(14, P3, a3, 0)
        }
        { // t5
          u64 w5 = WB(5);
          u64 a1 = mul2(w5, Y1), a2 = mul2(w5, Y2), a3 = mul2(w5, Y3);
          ACC2(15, P2, a2, 6) ACC2(16, P2, a3, 7) ACC2(17, P2, a1, 5) ACC2(18, P3, a2, 7)
          ACC2(19, P1, a2, 5) ACC2(20, P3, a3, 6) ACC2(21, P1, a1, 6) ACC2(22, P3, a3, 8)
          ACC2(23, P1, a1, 8) ACC2(24, P3, a1, 4) ACC2(25, P1, a3, 4)
        }
        { // t6
          u64 w6 = WB(6);
          u64 a4 = mul2(w6, Y4), a5 = mul2(w6, Y5), a6 = mul2(w6, Y6);
          u64 a7 = mul2(w6, Y7), a8 = mul2(w6, Y8);
          ACC2(26, P2, a6, 2) ACC2(27, P2, a7, 3) ACC2(28, P2, a5, 1) ACC2(29, P3, a6, 3)
          ACC2(30, P1, a6, 1) ACC2(31, P3, a7, 2) ACC2(32, P1, a5, 2) ACC2(33, P3, a8, 3)
          ACC2(34, P1, a8, 1) ACC2(35, P3, a4, 1) ACC2(36, P1, a4, 3)
        }
      }

      // ---- phase 3: P4..P8 (l=2 input) ----
      {
        u64 P4 = pack2(sa[128 + 5*lane    ], sbp[128 + 5*lane    ]);
        u64 P5 = pack2(sa[128 + 5*lane + 1], sbp[128 + 5*lane + 1]);
        u64 P6 = pack2(sa[128 + 5*lane + 2], sbp[128 + 5*lane + 2]);
        u64 P7 = pack2(sa[128 + 5*lane + 3], sbp[128 + 5*lane + 3]);
        u64 P8 = pack2(sa[128 + 5*lane + 4], sbp[128 + 5*lane + 4]);
        { // t7
          u64 a0 = mul2(WB(7), Y0);
          ACC2(37, P4, a0, 4) ACC2(38, P5, a0, 5) ACC2(39, P6, a0, 6)
          ACC2(40, P7, a0, 7) ACC2(41, P8, a0, 8)
        }
        { // t8
          u64 w8 = WB(8);
          u64 a1 = mul2(w8, Y1), a2 = mul2(w8, Y2), a3 = mul2(w8, Y3);
          ACC2(42, P6, a2, 2) ACC2(43, P6, a3, 3) ACC2(44, P6, a1, 1) ACC2(45, P7, a2, 3)
          ACC2(46, P5, a2, 1) ACC2(47, P7, a3, 2) ACC2(48, P5, a1, 2) ACC2(49, P8, a3, 3)
          ACC2(50, P8, a1, 1) ACC2(51, P4, a3, 1) ACC2(52, P4, a1, 3)
        }
        { // t9
          u64 w9 = WB(9);
          u64 a4 = mul2(w9, Y4), a5 = mul2(w9, Y5), a6 = mul2(w9, Y6);
          u64 a7 = mul2(w9, Y7), a8 = mul2(w9, Y8);
          ACC2(53, P4, a4, 0) ACC2(54, P5, a5, 0) ACC2(55, P6, a6, 0)
          ACC2(56, P7, a7, 0) ACC2(57, P8, a8, 0)
        }
        { // t10
          u64 w10 = WB(10);
          u64 a4 = mul2(w10, Y4), a5 = mul2(w10, Y5), a6 = mul2(w10, Y6);
          u64 a7 = mul2(w10, Y7), a8 = mul2(w10, Y8);
          ACC2(58, P6, a6, 6) ACC2(59, P6, a7, 7) ACC2(60, P6, a5, 5) ACC2(61, P7, a6, 7)
          ACC2(62, P5, a6, 5) ACC2(63, P6, a8, 8) ACC2(64, P6, a4, 4) ACC2(65, P8, a6, 8)
          ACC2(66, P4, a6, 4) ACC2(67, P7, a7, 6) ACC2(68, P5, a5, 6) ACC2(69, P7, a7, 8)
          ACC2(70, P5, a5, 8) ACC2(71, P7, a5, 4) ACC2(72, P5, a7, 4) ACC2(73, P7, a8, 7)
          ACC2(74, P5, a8, 5) ACC2(75, P7, a4, 5) ACC2(76, P5, a4, 7) ACC2(77, P8, a7, 7)
          ACC2(78, P4, a7, 5) ACC2(79, P8, a5, 5) ACC2(80, P4, a5, 7) ACC2(81, P8, a8, 6)
          ACC2(82, P4, a4, 6)
        }
      }
#undef ACC2
#undef YPK
#undef WB

      // unpack + scatter both rows into smem
      float aL, bL;
      unpack2(o0, aL, bL); sa[lane] = aL;               sbp[lane] = bL;
      unpack2(o1, aL, bL); sa[32 + 3*lane] = aL;        sbp[32 + 3*lane] = bL;
      unpack2(o2, aL, bL); sa[32 + 3*lane + 1] = aL;    sbp[32 + 3*lane + 1] = bL;
      unpack2(o3, aL, bL); sa[32 + 3*lane + 2] = aL;    sbp[32 + 3*lane + 2] = bL;
      unpack2(o4, aL, bL); sa[128 + 5*lane] = aL;       sbp[128 + 5*lane] = bL;
      unpack2(o5, aL, bL); sa[128 + 5*lane + 1] = aL;   sbp[128 + 5*lane + 1] = bL;
      unpack2(o6, aL, bL); sa[128 + 5*lane + 2] = aL;   sbp[128 + 5*lane + 2] = bL;
      unpack2(o7, aL, bL); sa[128 + 5*lane + 3] = aL;   sbp[128 + 5*lane + 3] = bL;
      unpack2(o8, aL, bL); sa[128 + 5*lane + 4] = aL;   sbp[128 + 5*lane + 4] = bL;
      __syncwarp();

      // drain both rows: smem float4 -> global float4
      {
        float4* __restrict__ dst = (float4*)(OUT + (size_t)rA * 1152);
        float4* s4 = cur[0];
        if (lane < 8)  dst[8*q + lane]             = s4[lane];
        if (lane < 24) dst[32 + 24*q + lane]       = s4[8 + lane];
        dst[128 + 40*q + lane]                     = s4[32 + lane];
        if (lane < 8)  dst[128 + 40*q + 32 + lane] = s4[64 + lane];
      }
      if (okB) {
        float4* __restrict__ dst = (float4*)(OUT + (size_t)(rA+1) * 1152);
        float4* s4 = cur[1];
        if (lane < 8)  dst[8*q + lane]             = s4[lane];
        if (lane < 24) dst[32 + 24*q + lane]       = s4[8 + lane];
        dst[128 + 40*q + lane]                     = s4[32 + lane];
        if (lane < 8)  dst[128 + 40*q + 32 + lane] = s4[64 + lane];
      }
    }
    __syncwarp();
  }
}

// ---------------------------------------------------------------------------
extern "C" void kernel_launch(void* const* d_in, const int* in_sizes, int n_in,
                              void* d_out, int out_size)
{
  const float* x1 = (const float*)d_in[0];
  const float* x2 = (const float*)d_in[1];
  const float* w  = (const float*)d_in[2];
  if (n_in >= 3) {
    int iw = -1, imax = -1;
    long long smax = -1;
    for (int i = 0; i < 3; ++i) {
      if (in_sizes[i] == 1408) iw = i;
      if ((long long)in_sizes[i] > smax) { smax = in_sizes[i]; imax = i; }
    }
    if (iw >= 0 && imax >= 0 && iw != imax) {
      int ix2 = 3 - iw - imax;
      x1 = (const float*)d_in[imax];
      x2 = (const float*)d_in[ix2];
      w  = (const float*)d_in[iw];
    }
  }

  int Z = in_sizes[0] > in_sizes[1]
            ? (in_sizes[0] > in_sizes[2] ? in_sizes[0] : in_sizes[2])
            : (in_sizes[1] > in_sizes[2] ? in_sizes[1] : in_sizes[2]);
  Z /= 1152;

  Coefs coef;
  compute_coefs(&coef);

  int grid = (Z + 15) / 16;
  tp_kernel<<<grid, 256>>>(x1, x2, w, (float*)d_out, Z, coef);
}